// round 6
// baseline (speedup 1.0000x reference)
#include <cuda_runtime.h>

#define TB 8192   // batch
#define TT 512    // seq len
#define DD 8      // input size
#define HH 64     // hidden
#define RP 36     // row stride (floats): 144B
#define NT 256    // threads: u = tid&63 (unit), rg = tid>>6 (row group of 8 rows)

// Gate-interleaved transposed weights WTg[k][u][gate] + interleaved biases.
#define WT_TOTAL 185856
__device__ float g_wt[WT_TOTAL];

struct WSrcs { const float* p[18]; };
__constant__ int c_woff[19] = {0, 2048, 18432, 34816, 51200, 67584, 83968,
                               102400, 118784, 135168, 151552, 167936, 184320,
                               184576, 184832, 185088, 185344, 185600, 185856};

__global__ void transpose_all(WSrcs ws) {
    int idx = blockIdx.x * blockDim.x + threadIdx.x;
    if (idx >= WT_TOTAL) return;
    int seg = 0;
    #pragma unroll
    for (int i = 1; i < 18; i++) seg += (idx >= c_woff[i]);
    int off  = c_woff[seg];
    int cols = (c_woff[seg + 1] - off) >> 8;   // 1 for bias segments
    int pos = idx - off;
    int k = pos >> 8, rem = pos & 255, u = rem >> 2, g = rem & 3;
    g_wt[idx] = ws.p[seg][(g * HH + u) * cols + k];
}

__device__ __forceinline__ float tanh_fast(float x) {
    float y;
    asm("tanh.approx.f32 %0, %1;" : "=f"(y) : "f"(x));
    return y;
}
__device__ __forceinline__ float sig_fast(float x) {
    return fmaf(0.5f, tanh_fast(0.5f * x), 0.5f);
}

__device__ __forceinline__ unsigned long long pack2(float w) {
    unsigned long long p;
    asm("mov.b64 %0, {%1, %1};" : "=l"(p) : "f"(w));
    return p;
}
__device__ __forceinline__ void fma2(unsigned long long& acc, unsigned long long a,
                                     unsigned long long b) {
    asm("fma.rn.f32x2 %0, %1, %2, %0;" : "+l"(acc) : "l"(a), "l"(b));
}
__device__ __forceinline__ void unpack2(unsigned long long p, float& lo, float& hi) {
    asm("mov.b64 {%0, %1}, %2;" : "=f"(lo), "=f"(hi) : "l"(p));
}

// warp-pair barrier: row group rg <-> warps 2rg, 2rg+1 (64 threads), ids 1..4
__device__ __forceinline__ void pair_bar(int rg) {
    asm volatile("bar.sync %0, 64;" :: "r"(rg + 1) : "memory");
}

// acc[g*4+q] += WTg[k][u][g] * buf[k][rg*8 + 2q..2q+1]
__device__ __forceinline__ void gemv4(unsigned long long acc[16],
                                      const float* __restrict__ WTg, int K,
                                      const float* __restrict__ buf,
                                      int u, int rg) {
    #pragma unroll 4
    for (int k = 0; k < K; k++) {
        float4 w4 = *(const float4*)(WTg + k * 256 + u * 4);   // 512B/warp LDG.128
        unsigned long long wi = pack2(w4.x), wf = pack2(w4.y);
        unsigned long long wg = pack2(w4.z), wo = pack2(w4.w);
        const ulonglong2* xp = (const ulonglong2*)(buf + k * RP + rg * 8);
        ulonglong2 v01 = xp[0];                 // broadcast LDS.128
        ulonglong2 v23 = xp[1];
        fma2(acc[0],  wi, v01.x); fma2(acc[1],  wi, v01.y);
        fma2(acc[2],  wi, v23.x); fma2(acc[3],  wi, v23.y);
        fma2(acc[4],  wf, v01.x); fma2(acc[5],  wf, v01.y);
        fma2(acc[6],  wf, v23.x); fma2(acc[7],  wf, v23.y);
        fma2(acc[8],  wg, v01.x); fma2(acc[9],  wg, v01.y);
        fma2(acc[10], wg, v23.x); fma2(acc[11], wg, v23.y);
        fma2(acc[12], wo, v01.x); fma2(acc[13], wo, v01.y);
        fma2(acc[14], wo, v23.x); fma2(acc[15], wo, v23.y);
    }
}

// One LSTM layer step: gemv -> register state update -> h store -> pair barrier.
__device__ __forceinline__ void layer_step(const float* __restrict__ WTi, int Ki,
                                           const float* __restrict__ inbuf,
                                           const float* __restrict__ WTi2,
                                           const float* __restrict__ inbuf2,
                                           const float* __restrict__ WTh,
                                           const float* __restrict__ hprev,
                                           const float* __restrict__ Bint,
                                           float* __restrict__ c_reg,
                                           float* __restrict__ hout,
                                           int u, int rg) {
    unsigned long long acc[16];
    {
        float4 b4 = *(const float4*)(Bint + u * 4);
        unsigned long long bi = pack2(b4.x), bf = pack2(b4.y);
        unsigned long long bg = pack2(b4.z), bo = pack2(b4.w);
        acc[0] = acc[1] = acc[2] = acc[3] = bi;
        acc[4] = acc[5] = acc[6] = acc[7] = bf;
        acc[8] = acc[9] = acc[10] = acc[11] = bg;
        acc[12] = acc[13] = acc[14] = acc[15] = bo;
    }
    gemv4(acc, WTi, Ki, inbuf, u, rg);
    if (inbuf2) gemv4(acc, WTi2, HH, inbuf2, u, rg);
    gemv4(acc, WTh, HH, hprev, u, rg);

    float hv[8];
    #pragma unroll
    for (int q = 0; q < 4; q++) {
        float i0, i1, f0, f1, g0, g1, o0, o1;
        unpack2(acc[q],      i0, i1);
        unpack2(acc[4 + q],  f0, f1);
        unpack2(acc[8 + q],  g0, g1);
        unpack2(acc[12 + q], o0, o1);
        float c;
        c = c_reg[2 * q];
        c = sig_fast(f0) * c + sig_fast(i0) * tanh_fast(g0);
        hv[2 * q] = sig_fast(o0) * tanh_fast(c);
        c_reg[2 * q] = c;
        c = c_reg[2 * q + 1];
        c = sig_fast(f1) * c + sig_fast(i1) * tanh_fast(g1);
        hv[2 * q + 1] = sig_fast(o1) * tanh_fast(c);
        c_reg[2 * q + 1] = c;
    }
    float4* hp = (float4*)(hout + u * RP + rg * 8);
    hp[0] = make_float4(hv[0], hv[1], hv[2], hv[3]);
    hp[1] = make_float4(hv[4], hv[5], hv[6], hv[7]);
    pair_bar(rg);
}

__global__ __launch_bounds__(NT, 2)
void lstm_main(const float* __restrict__ enc_x, const float* __restrict__ dec_x,
               const float* __restrict__ fcW, const float* __restrict__ fcb,
               float* __restrict__ out) {
    extern __shared__ float sm[];
    float* s_h  = sm;                     // [2 parity][3 layer][64][RP]
    float* s_x  = s_h + 2 * 3 * HH * RP;  // [2 parity][8][RP]
    float* s_fc = s_x + 2 * DD * RP;      // 512 fcW^T + 8 fcb

    int tid = threadIdx.x;
    int bid = blockIdx.x;
    int rg  = tid >> 6;                   // row group (8 rows), owned by warp pair

    // variable groups per CTA: bid<136 -> 4 groups, else 3. LUT[bid%148] pairing
    // puts a 4-CTA with a 3-CTA on each of 136 SMs (7 groups), 12 SMs get 6.
    int ng, startg;
    if (bid < 136) { ng = 4; startg = 4 * bid; }
    else           { ng = 3; startg = 3 * bid + 136; }
    if (rg >= ng) return;                 // inactive warp pairs exit
    int NTa = ng * 64;                    // active threads
    int b0  = startg * 8;                 // first batch row of this CTA

    int u = tid & 63;                     // hidden unit
    int xr = tid >> 3, xk = tid & 7;      // x staging coords (pair-local: xr>>3==rg)
    int pr = tid >> 3, pd = tid & 7;      // fc output coords (pair-local)

    for (int i = tid; i < 2 * 3 * HH * RP; i += NTa) s_h[i] = 0.f;
    for (int i = tid; i < DD * HH; i += NTa) {
        int uu = i >> 3, d = i & 7;
        s_fc[uu * 8 + d] = fcW[d * HH + uu];
    }
    if (tid < DD) s_fc[512 + tid] = fcb[tid];

    const float* WT_e0i = g_wt;           const float* WT_e0h = g_wt + 2048;
    const float* WT_e1i = g_wt + 18432;   const float* WT_e1h = g_wt + 34816;
    const float* WT_e2i = g_wt + 51200;   const float* WT_e2h = g_wt + 67584;
    const float* WT_d0i = g_wt + 83968;   const float* WT_d0h = g_wt + 102400;
    const float* WT_d1i = g_wt + 118784;  const float* WT_d1h = g_wt + 135168;
    const float* WT_d2i = g_wt + 151552;  const float* WT_d2h = g_wt + 167936;
    const float* B_e0 = g_wt + 184320;    const float* B_e1 = g_wt + 184576;
    const float* B_e2 = g_wt + 184832;    const float* B_d0 = g_wt + 185088;
    const float* B_d1 = g_wt + 185344;    const float* B_d2 = g_wt + 185600;

    float c0[8], c1[8], c2[8];
    #pragma unroll
    for (int i = 0; i < 8; i++) c0[i] = c1[i] = c2[i] = 0.f;

    const int LSZ = HH * RP;
    const size_t xbase = (size_t)(b0 + xr) * TT * DD + xk;
    int p = 0;

    // prologue: stage x(t=0) into s_x parity 0
    s_x[xk * RP + xr] = enc_x[xbase];
    __syncthreads();                      // one block-wide sync after init

    // ---------------- encoder ----------------
    for (int t = 0; t < TT; t++) {
        float* hc = s_h + p * 3 * LSZ;
        float* hv = s_h + (p ^ 1) * 3 * LSZ;
        const float* sx = s_x + p * DD * RP;
        // issue next-step x load early (enc t+1, or dec t=0 at the boundary)
        float xn = (t < TT - 1) ? enc_x[xbase + (size_t)(t + 1) * DD]
                                : dec_x[xbase];
        layer_step(WT_e0i, DD, sx,       nullptr, nullptr, WT_e0h, hv,           B_e0, c0, hc,           u, rg);
        layer_step(WT_e1i, HH, hc,       nullptr, nullptr, WT_e1h, hv + LSZ,     B_e1, c1, hc + LSZ,     u, rg);
        s_x[(p ^ 1) * DD * RP + xk * RP + xr] = xn;   // ordered by layer2's barrier
        layer_step(WT_e2i, HH, hc + LSZ, nullptr, nullptr, WT_e2h, hv + 2 * LSZ, B_e2, c2, hc + 2 * LSZ, u, rg);
        p ^= 1;
    }

    // ---------------- decoder ----------------
    for (int t = 0; t < TT; t++) {
        float* hc = s_h + p * 3 * LSZ;
        float* hv = s_h + (p ^ 1) * 3 * LSZ;
        const float* sx = s_x + p * DD * RP;
        int tn = (t + 1 < TT) ? t + 1 : t;
        float xn = dec_x[xbase + (size_t)tn * DD];
        const float* ybuf = (t > 0) ? (hv + 2 * LSZ) : nullptr;   // y_prev = prev h2
        layer_step(WT_d0i, DD, sx,       WT_d0i + DD * 256, ybuf, WT_d0h, hv,           B_d0, c0, hc,           u, rg);
        layer_step(WT_d1i, HH, hc,       nullptr, nullptr,  WT_d1h, hv + LSZ,     B_d1, c1, hc + LSZ,     u, rg);
        s_x[(p ^ 1) * DD * RP + xk * RP + xr] = xn;
        layer_step(WT_d2i, HH, hc + LSZ, nullptr, nullptr,  WT_d2h, hv + 2 * LSZ, B_d2, c2, hc + 2 * LSZ, u, rg);

        // pred = h2 @ fcW^T + fcb  (pair-local rows; ordered by layer2's pair barrier)
        const float* h2 = hc + 2 * LSZ;
        float a = s_fc[512 + pd];
        #pragma unroll 8
        for (int uu = 0; uu < HH; uu++)
            a = fmaf(s_fc[uu * 8 + pd], h2[uu * RP + pr], a);
        out[(size_t)(b0 + pr) * TT * DD + t * DD + pd] = a;
        p ^= 1;
    }
}

extern "C" void kernel_launch(void* const* d_in, const int* in_sizes, int n_in,
                              void* d_out, int out_size) {
    const float* enc_x = (const float*)d_in[0];
    const float* dec_x = (const float*)d_in[1];

    WSrcs ws;
    const int src_idx[18] = {2, 3, 5, 6, 8, 9, 11, 12, 14, 15, 17, 18,
                             4, 7, 10, 13, 16, 19};
    for (int i = 0; i < 18; i++) ws.p[i] = (const float*)d_in[src_idx[i]];
    transpose_all<<<(WT_TOTAL + 255) / 256, 256>>>(ws);

    size_t smem = (size_t)(2 * 3 * HH * RP + 2 * DD * RP + 520) * sizeof(float);
    cudaFuncSetAttribute(lstm_main, cudaFuncAttributeMaxDynamicSharedMemorySize, (int)smem);

    lstm_main<<<296, NT, smem>>>(enc_x, dec_x,
                                 (const float*)d_in[20], (const float*)d_in[21],
                                 (float*)d_out);
}